// round 1
// baseline (speedup 1.0000x reference)
#include <cuda_runtime.h>
#include <cuda_bf16.h>

// Sizes (fixed for this problem)
// B=64, T=1024, D=512, H=256, 4H=1024, two directions.

// ---------------------------------------------------------------------------
// Scratch (device globals -- no allocation allowed)
// ---------------------------------------------------------------------------
__device__ float G_buf [(size_t)65536 * 2048];        // [m = b*1024 + t][j(0..2047)]
__device__ float Gt_buf[(size_t)1024 * 2048 * 64];    // [t][j][b]
__device__ float h_glob[2][2][16384];                 // [phase][dir][k*64 + b]
__device__ volatile unsigned g_flag[2][64];           // per-direction per-CTA step flags

// ---------------------------------------------------------------------------
// f32x2 packed-math helpers (sm_100+: fma.rn.f32x2 doubles fp32 FMA rate)
// ---------------------------------------------------------------------------
static __device__ __forceinline__ unsigned long long pk2(float x, float y) {
    unsigned long long r;
    asm("mov.b64 %0, {%1, %2};" : "=l"(r) : "f"(x), "f"(y));
    return r;
}
static __device__ __forceinline__ unsigned long long fma2(
    unsigned long long a, unsigned long long b, unsigned long long c) {
    unsigned long long d;
    asm("fma.rn.f32x2 %0, %1, %2, %3;" : "=l"(d) : "l"(a), "l"(b), "l"(c));
    return d;
}
static __device__ __forceinline__ float2 upk(unsigned long long v) {
    float2 r;
    asm("mov.b64 {%0, %1}, %2;" : "=f"(r.x), "=f"(r.y) : "l"(v));
    return r;
}

static __device__ __forceinline__ float sigm_f(float x) {
    return __frcp_rn(1.f + __expf(-x));
}
static __device__ __forceinline__ float tanh_f(float x) {
    x = fminf(fmaxf(x, -15.f), 15.f);
    float e = __expf(2.f * x);
    return (e - 1.f) / (e + 1.f);
}

// ---------------------------------------------------------------------------
// Reset: zero h state (phase 0 and 1) and barrier flags. Runs every launch.
// ---------------------------------------------------------------------------
__global__ void reset_k() {
    unsigned i = blockIdx.x * 256u + threadIdx.x;
    float* h = &h_glob[0][0][0];
    if (i < 65536u) h[i] = 0.f;
    if (i < 128u) ((volatile unsigned*)&g_flag[0][0])[i] = 0u;
}

// ---------------------------------------------------------------------------
// Phase 1: G[m][j] = x[m,:] . Wih[j,:] + bih[j] + bhh[j]
// A: [65536,512] (== input), B rows: Wih_f (j<1024) / Wih_b (j>=1024)
// 128x128x8 tiles, 256 threads, 8x8 per-thread, f32x2 packed FMA.
// ---------------------------------------------------------------------------
__global__ void __launch_bounds__(256) gemm_in(
    const float* __restrict__ A,
    const float* __restrict__ Wf, const float* __restrict__ Wb,
    const float* __restrict__ bif, const float* __restrict__ bhf,
    const float* __restrict__ bib, const float* __restrict__ bhb)
{
    __shared__ float As[8][132];
    __shared__ float Bs[8][132];

    const int bn = blockIdx.x;          // 0..15 (16 * 128 = 2048 cols)
    const int bm = blockIdx.y;          // 0..511 (512 * 128 = 65536 rows)
    const bool fwd = (bn < 8);
    const float* Bm = fwd ? Wf : Wb;
    const int nloc = (bn & 7) * 128;    // col offset inside the direction

    const int tid = threadIdx.x;
    const int lr  = tid >> 1;           // 0..127
    const int lk  = (tid & 1) * 4;      // 0 or 4

    const float* Ap = A  + (size_t)(bm * 128 + lr) * 512 + lk;
    const float* Bp = Bm + (size_t)(nloc + lr) * 512 + lk;

    const int tx = tid & 15;            // n
    const int ty = tid >> 4;            // m

    unsigned long long acc[8][4];
#pragma unroll
    for (int i = 0; i < 8; i++)
#pragma unroll
        for (int j = 0; j < 4; j++) acc[i][j] = 0ull;

    float4 pa = *(const float4*)(Ap);
    float4 pb = *(const float4*)(Bp);

    for (int k0 = 0; k0 < 512; k0 += 8) {
        As[lk + 0][lr] = pa.x; As[lk + 1][lr] = pa.y;
        As[lk + 2][lr] = pa.z; As[lk + 3][lr] = pa.w;
        Bs[lk + 0][lr] = pb.x; Bs[lk + 1][lr] = pb.y;
        Bs[lk + 2][lr] = pb.z; Bs[lk + 3][lr] = pb.w;
        __syncthreads();

        if (k0 + 8 < 512) {                 // prefetch next K-slab (hides LDG)
            pa = *(const float4*)(Ap + k0 + 8);
            pb = *(const float4*)(Bp + k0 + 8);
        }

#pragma unroll
        for (int kk = 0; kk < 8; kk++) {
            float4 a0 = *(const float4*)&As[kk][ty * 8];
            float4 a1 = *(const float4*)&As[kk][ty * 8 + 4];
            float4 b0 = *(const float4*)&Bs[kk][tx * 8];
            float4 b1 = *(const float4*)&Bs[kk][tx * 8 + 4];
            unsigned long long bb[4] = {
                pk2(b0.x, b0.y), pk2(b0.z, b0.w),
                pk2(b1.x, b1.y), pk2(b1.z, b1.w)
            };
            float av[8] = {a0.x, a0.y, a0.z, a0.w, a1.x, a1.y, a1.z, a1.w};
#pragma unroll
            for (int i = 0; i < 8; i++) {
                unsigned long long aa = pk2(av[i], av[i]);
#pragma unroll
                for (int j = 0; j < 4; j++)
                    acc[i][j] = fma2(aa, bb[j], acc[i][j]);
            }
        }
        __syncthreads();
    }

    const float* bi = fwd ? bif : bib;
    const float* bh = fwd ? bhf : bhb;
    float bias[8];
#pragma unroll
    for (int j = 0; j < 8; j++) {
        int nl = nloc + tx * 8 + j;
        bias[j] = bi[nl] + bh[nl];
    }
#pragma unroll
    for (int i = 0; i < 8; i++) {
        int m = bm * 128 + ty * 8 + i;
        float* dst = G_buf + (size_t)m * 2048 + bn * 128 + tx * 8;
        float2 c0 = upk(acc[i][0]), c1 = upk(acc[i][1]);
        float2 c2 = upk(acc[i][2]), c3 = upk(acc[i][3]);
        float4 o0 = make_float4(c0.x + bias[0], c0.y + bias[1],
                                c1.x + bias[2], c1.y + bias[3]);
        float4 o1 = make_float4(c2.x + bias[4], c2.y + bias[5],
                                c3.x + bias[6], c3.y + bias[7]);
        *(float4*)dst = o0;
        *(float4*)(dst + 4) = o1;
    }
}

// ---------------------------------------------------------------------------
// Transpose G[b*1024+t][j] -> Gt[t][j][b] (so recurrence reads are b-coalesced)
// grid: (32 j-blocks of 64, 1024 t), 256 threads, 64x64 smem tile.
// ---------------------------------------------------------------------------
__global__ void __launch_bounds__(256) transp() {
    __shared__ float tile[64][65];
    const int t  = blockIdx.y;
    const int j0 = blockIdx.x * 64;
    const int tid = threadIdx.x;

    const int jq = (tid & 15) * 4;
    const int bb = tid >> 4;
#pragma unroll
    for (int p = 0; p < 4; p++) {
        int bi = bb + p * 16;
        float4 v = *(const float4*)(G_buf + ((size_t)(bi * 1024 + t)) * 2048 + j0 + jq);
        tile[bi][jq + 0] = v.x; tile[bi][jq + 1] = v.y;
        tile[bi][jq + 2] = v.z; tile[bi][jq + 3] = v.w;
    }
    __syncthreads();

    const int bq = (tid & 15) * 4;
    const int jj = tid >> 4;
#pragma unroll
    for (int p = 0; p < 4; p++) {
        int j = jj + p * 16;
        float4 v = make_float4(tile[bq + 0][j], tile[bq + 1][j],
                               tile[bq + 2][j], tile[bq + 3][j]);
        *(float4*)(Gt_buf + ((size_t)t * 2048 + j0 + j) * 64 + bq) = v;
    }
}

// ---------------------------------------------------------------------------
// Phase 2: persistent recurrence. 128 CTAs (64 per direction), 256 threads.
// CTA (dir, slice) owns h-indices q = slice*4 .. slice*4+3 (16 gate columns).
// thread = (b = tid&63, qt = tid>>6). Whh slice cached in smem as f32x2 pairs.
// Grid barrier per step: per-CTA flag store + 64-lane parallel poll.
// ---------------------------------------------------------------------------
__global__ void __launch_bounds__(256) recur(
    const float* __restrict__ Whf, const float* __restrict__ Whb,
    float* __restrict__ out)
{
    extern __shared__ float sm[];
    float* h_s = sm;                                   // [256][64] = 16384 f
    ulonglong2* w_s = (ulonglong2*)(sm + 16384);       // [4][256]

    const int cta   = blockIdx.x;
    const int dir   = cta >> 6;
    const int slice = cta & 63;
    const int qb    = slice * 4;
    const int tid   = threadIdx.x;
    const int b     = tid & 63;
    const int qt    = tid >> 6;
    const int q     = qb + qt;

    const float* W = dir ? Whb : Whf;
    // Load Whh rows for the 16 gate columns this CTA owns, packed (Wi,Wf)/(Wg,Wo)
    for (int idx = tid; idx < 1024; idx += 256) {
        int qq = idx >> 8;        // 0..3
        int k  = idx & 255;
        int qg = qb + qq;
        float wi = W[(size_t)(      qg) * 256 + k];
        float wf = W[(size_t)(256 + qg) * 256 + k];
        float wg = W[(size_t)(512 + qg) * 256 + k];
        float wo = W[(size_t)(768 + qg) * 256 + k];
        ulonglong2 v;
        v.x = pk2(wi, wf);
        v.y = pk2(wg, wo);
        w_s[qq * 256 + k] = v;
    }

    const ulonglong2* wrow = w_s + qt * 256;
    float c = 0.f;

    for (int step = 0; step < 1024; ++step) {
        const int t = dir ? (1023 - step) : step;

        // Stage h (64KB) from the current phase buffer; L2-only loads.
        {
            const float4* src = (const float4*)(&h_glob[step & 1][dir][0]);
            float4* dst = (float4*)h_s;
#pragma unroll
            for (int i = 0; i < 16; i++)
                dst[tid + i * 256] = __ldcg(src + tid + i * 256);
        }
        __syncthreads();

        // Gate pre-activations (b-coalesced)
        const float* gp = Gt_buf + ((size_t)t * 2048 + (size_t)dir * 1024) * 64 + b;
        float pi = __ldg(gp + (size_t)(      q) * 64);
        float pf = __ldg(gp + (size_t)(256 + q) * 64);
        float pg = __ldg(gp + (size_t)(512 + q) * 64);
        float po = __ldg(gp + (size_t)(768 + q) * 64);

        unsigned long long aif = pk2(pi, pf);
        unsigned long long ago = pk2(pg, po);

#pragma unroll 8
        for (int k = 0; k < 256; ++k) {
            float hv = h_s[k * 64 + b];
            ulonglong2 wv = wrow[k];
            unsigned long long hh = pk2(hv, hv);
            aif = fma2(hh, wv.x, aif);
            ago = fma2(hh, wv.y, ago);
        }

        float2 vif = upk(aif), vgo = upk(ago);
        float ig = sigm_f(vif.x);
        float fg = sigm_f(vif.y);
        float gg = tanh_f(vgo.x);
        float og = sigm_f(vgo.y);
        c = fg * c + ig * gg;
        float hn = og * tanh_f(c);

        out[((size_t)b * 1024 + t) * 512 + (size_t)dir * 256 + q] = hn;
        __stcg(&h_glob[(step + 1) & 1][dir][q * 64 + b], hn);

        if (step == 1023) break;

        // ---- grid barrier (per direction) ----
        __threadfence();
        __syncthreads();
        if (tid == 0) g_flag[dir][slice] = (unsigned)(step + 1);
        if (tid < 64) {
            while (g_flag[dir][tid] <= (unsigned)step) { __nanosleep(20); }
        }
        __syncthreads();
        __threadfence();
    }
}

// ---------------------------------------------------------------------------
// Launch
// ---------------------------------------------------------------------------
extern "C" void kernel_launch(void* const* d_in, const int* in_sizes, int n_in,
                              void* d_out, int out_size) {
    const float* x   = (const float*)d_in[0];
    const float* Wif = (const float*)d_in[1];
    const float* Whf = (const float*)d_in[2];
    const float* bif = (const float*)d_in[3];
    const float* bhf = (const float*)d_in[4];
    const float* Wib = (const float*)d_in[5];
    const float* Whb = (const float*)d_in[6];
    const float* bib = (const float*)d_in[7];
    const float* bhb = (const float*)d_in[8];
    float* out = (float*)d_out;

    cudaFuncSetAttribute(recur, cudaFuncAttributeMaxDynamicSharedMemorySize, 81920);

    reset_k<<<256, 256>>>();
    gemm_in<<<dim3(16, 512), 256>>>(x, Wif, Wib, bif, bhf, bib, bhb);
    transp<<<dim3(32, 1024), 256>>>();
    recur<<<128, 256, 81920>>>(Whf, Whb, out);
}